// round 1
// baseline (speedup 1.0000x reference)
#include <cuda_runtime.h>
#include <math.h>
#include <stdint.h>

// ---------------- problem constants ----------------
constexpr int BB = 32, TT = 256, VV = 30522, CC = 768, HH = 8, LL = 10;
constexpr int HS = CC / HH;     // 96
constexpr int FFD = 4 * CC;     // 3072
constexpr int BT = BB * TT;     // 8192
constexpr float LN_EPS = 1e-5f;

// ---------------- scratch (device globals; no runtime alloc) ----------------
__device__ float g_x[BT * CC];          // residual stream [B,T,C]
__device__ float g_h[BT * CC];          // layernorm output
__device__ float g_q[BT * CC];          // [B,H,T,HS]
__device__ float g_k[BT * CC];          // [B,H,T,HS]
__device__ float g_v[BT * CC];          // [B,H,T,HS]
__device__ float g_att[(size_t)BB * HH * TT * TT];   // [B,H,T,T]
__device__ float g_a[BT * CC];          // attn out [B,H,T,HS]
__device__ float g_at[BT * CC];         // attn out [B,T,C]
__device__ float g_ff[(size_t)BT * FFD];// [B*T, FF]
__device__ float g_rowloss[BT];

// ---------------- embedding ----------------
__global__ void embed_kernel(const int* __restrict__ idx,
                             const float* __restrict__ tok,
                             const float* __restrict__ pos,
                             float* __restrict__ x) {
    int i = blockIdx.x * blockDim.x + threadIdx.x;
    int total = BT * CC;
    if (i >= total) return;
    int bt = i / CC, c = i % CC;
    int t = bt % TT;
    x[i] = tok[(size_t)idx[bt] * CC + c] + pos[(size_t)t * CC + c];
}

// ---------------- layernorm (one block per row) ----------------
__global__ void ln_kernel(const float* __restrict__ x,
                          const float* __restrict__ g,
                          const float* __restrict__ b,
                          float* __restrict__ out) {
    int row = blockIdx.x;
    const float* xr = x + (size_t)row * CC;
    float* orow = out + (size_t)row * CC;
    __shared__ float red[256];
    __shared__ float s_mu, s_inv;
    int tid = threadIdx.x;

    float s = 0.f;
    for (int c = tid; c < CC; c += 256) s += xr[c];
    red[tid] = s; __syncthreads();
    for (int st = 128; st > 0; st >>= 1) { if (tid < st) red[tid] += red[tid + st]; __syncthreads(); }
    if (tid == 0) s_mu = red[0] / CC;
    __syncthreads();
    float mu = s_mu;

    float v = 0.f;
    for (int c = tid; c < CC; c += 256) { float d = xr[c] - mu; v += d * d; }
    red[tid] = v; __syncthreads();
    for (int st = 128; st > 0; st >>= 1) { if (tid < st) red[tid] += red[tid + st]; __syncthreads(); }
    if (tid == 0) s_inv = rsqrtf(red[0] / CC + LN_EPS);
    __syncthreads();
    float inv = s_inv;

    for (int c = tid; c < CC; c += 256)
        orow[c] = (xr[c] - mu) * inv * g[c] + b[c];
}

// ---------------- generic tiled GEMM ----------------
// C[M,N] = alpha * A[M,K] @ B (+bias) (+relu) (+=C if ACC)
// TB:    B is [N,K] row-major (compute A @ B^T)
// QKV:   epilogue scatters [B*T, C]-indexed output into [B,H,T,HS] layout
// batched via blockIdx.z with element strides sA/sB/sC
template<bool TB, bool BIAS, bool RELU, bool ACC, bool QKV>
__global__ void gemm_k(const float* __restrict__ A, const float* __restrict__ Bm,
                       const float* __restrict__ bias, float* __restrict__ Cm,
                       int M, int N, int K, float alpha,
                       size_t sA, size_t sB, size_t sC) {
    const float* Ab = A + (size_t)blockIdx.z * sA;
    const float* Bb = Bm + (size_t)blockIdx.z * sB;
    float* Cb = Cm + (size_t)blockIdx.z * sC;

    __shared__ float As[16][64];
    __shared__ float Bs[16][64];

    int bm = blockIdx.y * 64;
    int bn = blockIdx.x * 64;
    int tid = threadIdx.x;
    int tx = tid & 15, ty = tid >> 4;

    float acc[4][4] = {};

    for (int k0 = 0; k0 < K; k0 += 16) {
        // load A tile [64 rows][16 k] -> As[k][row]
        {
            int r = tid >> 2, c = (tid & 3) * 4;
            int gm = bm + r;
            #pragma unroll
            for (int i = 0; i < 4; i++) {
                int gk = k0 + c + i;
                As[c + i][r] = (gm < M && gk < K) ? Ab[(size_t)gm * K + gk] : 0.f;
            }
        }
        if (!TB) {
            // B [K,N]: tile rows k0..k0+15, cols bn..bn+63 -> Bs[k][n]
            int r = tid >> 4, c = (tid & 15) * 4;
            #pragma unroll
            for (int i = 0; i < 4; i++) {
                int gk = k0 + r, gn = bn + c + i;
                Bs[r][c + i] = (gk < K && gn < N) ? Bb[(size_t)gk * N + gn] : 0.f;
            }
        } else {
            // B [N,K]: Bs[k][n] = B[(bn+n)*K + k0+k]
            int n = tid >> 2, c = (tid & 3) * 4;
            #pragma unroll
            for (int i = 0; i < 4; i++) {
                int gk = k0 + c + i, gn = bn + n;
                Bs[c + i][n] = (gk < K && gn < N) ? Bb[(size_t)gn * K + gk] : 0.f;
            }
        }
        __syncthreads();

        #pragma unroll
        for (int k = 0; k < 16; k++) {
            float a4[4], b4[4];
            #pragma unroll
            for (int i = 0; i < 4; i++) a4[i] = As[k][ty * 4 + i];
            #pragma unroll
            for (int j = 0; j < 4; j++) b4[j] = Bs[k][tx * 4 + j];
            #pragma unroll
            for (int i = 0; i < 4; i++)
                #pragma unroll
                for (int j = 0; j < 4; j++)
                    acc[i][j] = fmaf(a4[i], b4[j], acc[i][j]);
        }
        __syncthreads();
    }

    #pragma unroll
    for (int i = 0; i < 4; i++) {
        int row = bm + ty * 4 + i;
        if (row >= M) continue;
        #pragma unroll
        for (int j = 0; j < 4; j++) {
            int col = bn + tx * 4 + j;
            if (col >= N) continue;
            float v = acc[i][j] * alpha;
            if (BIAS) v += bias[col];
            if (RELU) v = fmaxf(v, 0.f);
            size_t oidx;
            if (QKV) {
                int b = row / TT, t = row % TT, h = col / HS, d = col % HS;
                oidx = (((size_t)b * HH + h) * TT + t) * HS + d;
            } else {
                oidx = (size_t)row * N + col;
            }
            if (ACC) Cb[oidx] += v; else Cb[oidx] = v;
        }
    }
}

// ---------------- causal softmax over att rows (blockDim == TT) ----------------
__global__ void softmax_kernel(float* __restrict__ att) {
    size_t row = blockIdx.x;
    int qi = (int)(row % TT);
    float* w = att + row * (size_t)TT;
    int tid = threadIdx.x;
    __shared__ float red[256];
    __shared__ float s_mx, s_sum;

    float val = (tid <= qi) ? w[tid] : -1e30f;
    red[tid] = val; __syncthreads();
    for (int st = 128; st > 0; st >>= 1) { if (tid < st) red[tid] = fmaxf(red[tid], red[tid + st]); __syncthreads(); }
    if (tid == 0) s_mx = red[0];
    __syncthreads();
    float mx = s_mx;

    float e = (tid <= qi) ? expf(val - mx) : 0.f;
    red[tid] = e; __syncthreads();
    for (int st = 128; st > 0; st >>= 1) { if (tid < st) red[tid] += red[tid + st]; __syncthreads(); }
    if (tid == 0) s_sum = red[0];
    __syncthreads();

    w[tid] = e / s_sum;
}

// ---------------- [B,H,T,HS] -> [B,T,C] ----------------
__global__ void transpose_kernel(const float* __restrict__ a, float* __restrict__ at) {
    int i = blockIdx.x * blockDim.x + threadIdx.x;
    if (i >= BT * CC) return;
    int bt = i / CC, c = i % CC;
    int b = bt / TT, t = bt % TT, h = c / HS, d = c % HS;
    at[i] = a[(((size_t)b * HH + h) * TT + t) * HS + d];
}

// ---------------- loss: per-row logsumexp + gather ----------------
__global__ void rowloss_kernel(const float* __restrict__ logits,
                               const int* __restrict__ targets,
                               float* __restrict__ rowloss) {
    int r = blockIdx.x;
    const float* lr = logits + (size_t)r * VV;
    int tid = threadIdx.x;
    __shared__ float red[256];
    __shared__ float s_mx, s_sum;

    float mx = -1e30f;
    for (int c = tid; c < VV; c += 256) mx = fmaxf(mx, lr[c]);
    red[tid] = mx; __syncthreads();
    for (int st = 128; st > 0; st >>= 1) { if (tid < st) red[tid] = fmaxf(red[tid], red[tid + st]); __syncthreads(); }
    if (tid == 0) s_mx = red[0];
    __syncthreads();
    mx = s_mx;

    float s = 0.f;
    for (int c = tid; c < VV; c += 256) s += expf(lr[c] - mx);
    red[tid] = s; __syncthreads();
    for (int st = 128; st > 0; st >>= 1) { if (tid < st) red[tid] += red[tid + st]; __syncthreads(); }
    if (tid == 0) {
        int t = targets[r];
        rowloss[r] = -(lr[t] - mx - logf(red[0]));
    }
}

__global__ void lossreduce_kernel(const float* __restrict__ rowloss, float* __restrict__ out) {
    __shared__ float red[256];
    int tid = threadIdx.x;
    float s = 0.f;
    for (int r = tid; r < BT; r += 256) s += rowloss[r];
    red[tid] = s; __syncthreads();
    for (int st = 128; st > 0; st >>= 1) { if (tid < st) red[tid] += red[tid + st]; __syncthreads(); }
    if (tid == 0) out[0] = red[0] / BT;
}

// ---------------- host orchestration ----------------
static inline dim3 ggrid(int M, int N, int batch) {
    return dim3((N + 63) / 64, (M + 63) / 64, batch);
}

extern "C" void kernel_launch(void* const* d_in, const int* in_sizes, int n_in,
                              void* d_out, int out_size) {
    const int*   idx     = (const int*)  d_in[0];
    const int*   targets = (const int*)  d_in[1];
    const float* tok_emb = (const float*)d_in[2];
    const float* pos_emb = (const float*)d_in[3];
    const float* Wq      = (const float*)d_in[4];
    const float* Wk      = (const float*)d_in[5];
    const float* Wv      = (const float*)d_in[6];
    const float* Wproj   = (const float*)d_in[7];
    const float* bproj   = (const float*)d_in[8];
    const float* W1      = (const float*)d_in[9];
    const float* b1      = (const float*)d_in[10];
    const float* W2      = (const float*)d_in[11];
    const float* b2      = (const float*)d_in[12];
    const float* ln1_g   = (const float*)d_in[13];
    const float* ln1_b   = (const float*)d_in[14];
    const float* ln2_g   = (const float*)d_in[15];
    const float* ln2_b   = (const float*)d_in[16];
    const float* lnf_g   = (const float*)d_in[17];
    const float* lnf_b   = (const float*)d_in[18];
    const float* Wlm     = (const float*)d_in[19];
    const float* blm     = (const float*)d_in[20];
    float* out = (float*)d_out;

    float* x  = nullptr; cudaGetSymbolAddress((void**)&x,  g_x);
    float* h  = nullptr; cudaGetSymbolAddress((void**)&h,  g_h);
    float* q  = nullptr; cudaGetSymbolAddress((void**)&q,  g_q);
    float* k  = nullptr; cudaGetSymbolAddress((void**)&k,  g_k);
    float* v  = nullptr; cudaGetSymbolAddress((void**)&v,  g_v);
    float* att= nullptr; cudaGetSymbolAddress((void**)&att,g_att);
    float* a  = nullptr; cudaGetSymbolAddress((void**)&a,  g_a);
    float* at = nullptr; cudaGetSymbolAddress((void**)&at, g_at);
    float* ff = nullptr; cudaGetSymbolAddress((void**)&ff, g_ff);
    float* rowloss = nullptr; cudaGetSymbolAddress((void**)&rowloss, g_rowloss);

    const float rs = rsqrtf((float)HS);

    // embed
    embed_kernel<<<(BT * CC + 255) / 256, 256>>>(idx, tok_emb, pos_emb, x);

    for (int l = 0; l < LL; l++) {
        const float* wq = Wq + (size_t)l * CC * CC;
        const float* wk = Wk + (size_t)l * CC * CC;
        const float* wv = Wv + (size_t)l * CC * CC;
        const float* wp = Wproj + (size_t)l * CC * CC;
        const float* bp = bproj + (size_t)l * CC;
        const float* w1 = W1 + (size_t)l * CC * FFD;
        const float* bb1 = b1 + (size_t)l * FFD;
        const float* w2 = W2 + (size_t)l * FFD * CC;
        const float* bb2 = b2 + (size_t)l * CC;

        // ln1
        ln_kernel<<<BT, 256>>>(x, ln1_g + (size_t)l * CC, ln1_b + (size_t)l * CC, h);

        // QKV projections -> [B,H,T,HS]
        gemm_k<false,false,false,false,true><<<ggrid(BT, CC, 1), 256>>>(h, wq, nullptr, q, BT, CC, CC, 1.f, 0, 0, 0);
        gemm_k<false,false,false,false,true><<<ggrid(BT, CC, 1), 256>>>(h, wk, nullptr, k, BT, CC, CC, 1.f, 0, 0, 0);
        gemm_k<false,false,false,false,true><<<ggrid(BT, CC, 1), 256>>>(h, wv, nullptr, v, BT, CC, CC, 1.f, 0, 0, 0);

        // scores = Q @ K^T * rs  (batched over B*H)
        gemm_k<true,false,false,false,false><<<ggrid(TT, TT, BB * HH), 256>>>(
            q, k, nullptr, att, TT, TT, HS, rs,
            (size_t)TT * HS, (size_t)TT * HS, (size_t)TT * TT);

        // causal softmax
        softmax_kernel<<<BB * HH * TT, 256>>>(att);

        // A = softmax @ V  (batched)
        gemm_k<false,false,false,false,false><<<ggrid(TT, HS, BB * HH), 256>>>(
            att, v, nullptr, a, TT, HS, TT, 1.f,
            (size_t)TT * TT, (size_t)TT * HS, (size_t)TT * HS);

        // [B,H,T,HS] -> [B,T,C]
        transpose_kernel<<<(BT * CC + 255) / 256, 256>>>(a, at);

        // x += at @ Wproj + bproj
        gemm_k<false,true,false,true,false><<<ggrid(BT, CC, 1), 256>>>(at, wp, bp, x, BT, CC, CC, 1.f, 0, 0, 0);

        // ln2
        ln_kernel<<<BT, 256>>>(x, ln2_g + (size_t)l * CC, ln2_b + (size_t)l * CC, h);

        // ff = relu(h @ W1 + b1)
        gemm_k<false,true,true,false,false><<<ggrid(BT, FFD, 1), 256>>>(h, w1, bb1, ff, BT, FFD, CC, 1.f, 0, 0, 0);

        // x += ff @ W2 + b2
        gemm_k<false,true,false,true,false><<<ggrid(BT, CC, 1), 256>>>(ff, w2, bb2, x, BT, CC, FFD, 1.f, 0, 0, 0);
    }

    // final layernorm
    ln_kernel<<<BT, 256>>>(x, lnf_g, lnf_b, h);

    // logits = h @ Wlm + blm  -> d_out
    gemm_k<false,true,false,false,false><<<ggrid(BT, VV, 1), 256>>>(h, Wlm, blm, out, BT, VV, CC, 1.f, 0, 0, 0);

    // loss
    rowloss_kernel<<<BT, 256>>>(out, targets, rowloss);
    if ((long long)out_size > (long long)BT * VV) {
        lossreduce_kernel<<<1, 256>>>(rowloss, out + (size_t)BT * VV);
    }
}

// round 2
// speedup vs baseline: 2.6690x; 2.6690x over previous
#include <cuda_runtime.h>
#include <math.h>
#include <stdint.h>

// ---------------- problem constants ----------------
constexpr int BB = 32, TT = 256, VV = 30522, CC = 768, HH = 8, LL = 10;
constexpr int HS = CC / HH;     // 96
constexpr int FFD = 4 * CC;     // 3072
constexpr int BT = BB * TT;     // 8192
constexpr float LN_EPS = 1e-5f;

// ---------------- scratch (device globals; no runtime alloc) ----------------
__device__ float g_x[BT * CC];
__device__ float g_h[BT * CC];
__device__ float g_q[BT * CC];          // [B,H,T,HS]
__device__ float g_k[BT * CC];          // [B,H,T,HS]
__device__ float g_v[BT * CC];          // [B,H,T,HS]
__device__ float g_att[(size_t)BB * HH * TT * TT];
__device__ float g_a[BT * CC];          // [B,H,T,HS]
__device__ float g_at[BT * CC];         // [B,T,C]
__device__ float g_ff[(size_t)BT * FFD];
__device__ float g_rowloss[BT];

__device__ __forceinline__ float to_tf32(float x) {
    uint32_t u;
    asm("cvt.rna.tf32.f32 %0, %1;" : "=r"(u) : "f"(x));
    return __uint_as_float(u);
}

__device__ __forceinline__ void mma_tf32(float d[4], const uint32_t a[4], const uint32_t b[2]) {
    asm volatile(
        "mma.sync.aligned.m16n8k8.row.col.f32.tf32.tf32.f32 "
        "{%0,%1,%2,%3}, {%4,%5,%6,%7}, {%8,%9}, {%0,%1,%2,%3};\n"
        : "+f"(d[0]), "+f"(d[1]), "+f"(d[2]), "+f"(d[3])
        : "r"(a[0]), "r"(a[1]), "r"(a[2]), "r"(a[3]), "r"(b[0]), "r"(b[1]));
}

// ---------------- embedding ----------------
__global__ void embed_kernel(const int* __restrict__ idx,
                             const float* __restrict__ tok,
                             const float* __restrict__ pos,
                             float* __restrict__ x) {
    int i = blockIdx.x * blockDim.x + threadIdx.x;
    if (i >= BT * CC) return;
    int bt = i / CC, c = i % CC;
    int t = bt % TT;
    x[i] = tok[(size_t)idx[bt] * CC + c] + pos[(size_t)t * CC + c];
}

// ---------------- layernorm ----------------
__global__ void ln_kernel(const float* __restrict__ x,
                          const float* __restrict__ g,
                          const float* __restrict__ b,
                          float* __restrict__ out) {
    int row = blockIdx.x;
    const float* xr = x + (size_t)row * CC;
    float* orow = out + (size_t)row * CC;
    __shared__ float red[256];
    __shared__ float s_mu, s_inv;
    int tid = threadIdx.x;

    float s = 0.f;
    for (int c = tid; c < CC; c += 256) s += xr[c];
    red[tid] = s; __syncthreads();
    for (int st = 128; st > 0; st >>= 1) { if (tid < st) red[tid] += red[tid + st]; __syncthreads(); }
    if (tid == 0) s_mu = red[0] / CC;
    __syncthreads();
    float mu = s_mu;

    float v = 0.f;
    for (int c = tid; c < CC; c += 256) { float d = xr[c] - mu; v += d * d; }
    red[tid] = v; __syncthreads();
    for (int st = 128; st > 0; st >>= 1) { if (tid < st) red[tid] += red[tid + st]; __syncthreads(); }
    if (tid == 0) s_inv = rsqrtf(red[0] / CC + LN_EPS);
    __syncthreads();
    float inv = s_inv;

    for (int c = tid; c < CC; c += 256)
        orow[c] = (xr[c] - mu) * inv * g[c] + b[c];
}

// ---------------- tensor-core GEMM (tf32 mma.sync m16n8k8) ----------------
// C[M,N] = alpha * A[M,K] @ B (+bias) (+relu) (+=C if ACC)
// TB: B stored [N,K] (compute A @ B^T). QKV: scatter output to [B,H,T,HS].
// Requirements satisfied by all call sites: M % 128 == 0, K % 16 == 0.
template<bool TB, bool BIAS, bool RELU, bool ACC, bool QKV>
__global__ __launch_bounds__(256, 2)
void gemm_tc(const float* __restrict__ A, const float* __restrict__ Bm,
             const float* __restrict__ bias, float* __restrict__ Cm,
             int M, int N, int K, float alpha,
             size_t sA, size_t sB, size_t sC) {
    constexpr int BM = 128, BN = 128, BK = 16;
    __shared__ float As[BM][BK + 4];    // stride 20: conflict-free for frag loads
    __shared__ float Bs[BK][BN + 8];    // stride 136: conflict-free for frag loads

    const float* Ab = A + (size_t)blockIdx.z * sA;
    const float* Bb = Bm + (size_t)blockIdx.z * sB;
    float* Cb = Cm + (size_t)blockIdx.z * sC;

    int bm = blockIdx.y * BM;
    int bn = blockIdx.x * BN;
    int tid = threadIdx.x;
    int wid = tid >> 5, lane = tid & 31;
    int wm = (wid & 1) * 64;     // 2 warps along M, tile 64
    int wn = (wid >> 1) * 32;    // 4 warps along N, tile 32
    int gq = lane >> 2;          // 0..7
    int cq = lane & 3;           // 0..3

    float acc[4][4][4];
    #pragma unroll
    for (int i = 0; i < 4; i++)
        #pragma unroll
        for (int j = 0; j < 4; j++)
            #pragma unroll
            for (int t = 0; t < 4; t++) acc[i][j][t] = 0.f;

    const bool bvecOK = (!TB) && (bn + BN <= N) && ((N & 3) == 0);

    for (int k0 = 0; k0 < K; k0 += BK) {
        // ---- stage A (128x16), vectorized, always in range ----
        #pragma unroll
        for (int r = 0; r < 2; r++) {
            int id = tid + r * 256;          // 0..511 float4 slots
            int m = id >> 2;
            int kk = (id & 3) * 4;
            float4 va = *reinterpret_cast<const float4*>(&Ab[(size_t)(bm + m) * K + k0 + kk]);
            As[m][kk + 0] = to_tf32(va.x);
            As[m][kk + 1] = to_tf32(va.y);
            As[m][kk + 2] = to_tf32(va.z);
            As[m][kk + 3] = to_tf32(va.w);
        }
        // ---- stage B (16x128) ----
        if (!TB) {
            #pragma unroll
            for (int r = 0; r < 2; r++) {
                int id = tid + r * 256;
                int kk = id >> 5;             // 0..15
                int n = (id & 31) * 4;        // 0..124
                if (bvecOK) {
                    float4 vb = *reinterpret_cast<const float4*>(&Bb[(size_t)(k0 + kk) * N + bn + n]);
                    Bs[kk][n + 0] = to_tf32(vb.x);
                    Bs[kk][n + 1] = to_tf32(vb.y);
                    Bs[kk][n + 2] = to_tf32(vb.z);
                    Bs[kk][n + 3] = to_tf32(vb.w);
                } else {
                    #pragma unroll
                    for (int j = 0; j < 4; j++) {
                        int gn = bn + n + j;
                        Bs[kk][n + j] = (gn < N) ? to_tf32(Bb[(size_t)(k0 + kk) * N + gn]) : 0.f;
                    }
                }
            }
        } else {
            #pragma unroll
            for (int r = 0; r < 2; r++) {
                int id = tid + r * 256;
                int n = id >> 2;              // 0..127
                int kk = (id & 3) * 4;
                if (bn + n < N) {
                    float4 vb = *reinterpret_cast<const float4*>(&Bb[(size_t)(bn + n) * K + k0 + kk]);
                    Bs[kk + 0][n] = to_tf32(vb.x);
                    Bs[kk + 1][n] = to_tf32(vb.y);
                    Bs[kk + 2][n] = to_tf32(vb.z);
                    Bs[kk + 3][n] = to_tf32(vb.w);
                } else {
                    Bs[kk + 0][n] = 0.f; Bs[kk + 1][n] = 0.f;
                    Bs[kk + 2][n] = 0.f; Bs[kk + 3][n] = 0.f;
                }
            }
        }
        __syncthreads();

        // ---- compute: 2 k8-steps ----
        #pragma unroll
        for (int kk = 0; kk < BK; kk += 8) {
            uint32_t af[4][4];
            uint32_t bf[4][2];
            #pragma unroll
            for (int i = 0; i < 4; i++) {
                int mr = wm + i * 16;
                af[i][0] = __float_as_uint(As[mr + gq][kk + cq]);
                af[i][1] = __float_as_uint(As[mr + gq + 8][kk + cq]);
                af[i][2] = __float_as_uint(As[mr + gq][kk + cq + 4]);
                af[i][3] = __float_as_uint(As[mr + gq + 8][kk + cq + 4]);
            }
            #pragma unroll
            for (int j = 0; j < 4; j++) {
                int nc = wn + j * 8 + gq;
                bf[j][0] = __float_as_uint(Bs[kk + cq][nc]);
                bf[j][1] = __float_as_uint(Bs[kk + cq + 4][nc]);
            }
            #pragma unroll
            for (int i = 0; i < 4; i++)
                #pragma unroll
                for (int j = 0; j < 4; j++)
                    mma_tf32(acc[i][j], af[i], bf[j]);
        }
        __syncthreads();
    }

    // ---- epilogue ----
    #pragma unroll
    for (int i = 0; i < 4; i++) {
        int r0 = bm + wm + i * 16 + gq;     // and r0+8
        #pragma unroll
        for (int j = 0; j < 4; j++) {
            int c0 = bn + wn + j * 8 + cq * 2;   // and c0+1 (N always even here)
            if (c0 >= N) continue;
            #pragma unroll
            for (int half = 0; half < 2; half++) {
                int row = r0 + half * 8;
                float v0 = acc[i][j][half * 2 + 0] * alpha;
                float v1 = acc[i][j][half * 2 + 1] * alpha;
                if (BIAS) { v0 += bias[c0]; v1 += bias[c0 + 1]; }
                if (RELU) { v0 = fmaxf(v0, 0.f); v1 = fmaxf(v1, 0.f); }
                size_t oidx;
                if (QKV) {
                    int b = row / TT, t = row % TT, h = c0 / HS, d = c0 % HS;
                    oidx = (((size_t)b * HH + h) * TT + t) * HS + d;
                } else {
                    oidx = (size_t)row * N + c0;
                }
                if (ACC) {
                    float2 old = *reinterpret_cast<float2*>(&Cb[oidx]);
                    v0 += old.x; v1 += old.y;
                }
                *reinterpret_cast<float2*>(&Cb[oidx]) = make_float2(v0, v1);
            }
        }
    }
}

// ---------------- causal softmax (blockDim == TT) ----------------
__global__ void softmax_kernel(float* __restrict__ att) {
    size_t row = blockIdx.x;
    int qi = (int)(row % TT);
    float* w = att + row * (size_t)TT;
    int tid = threadIdx.x;
    __shared__ float red[256];
    __shared__ float s_mx, s_sum;

    float val = (tid <= qi) ? w[tid] : -1e30f;
    red[tid] = val; __syncthreads();
    for (int st = 128; st > 0; st >>= 1) { if (tid < st) red[tid] = fmaxf(red[tid], red[tid + st]); __syncthreads(); }
    if (tid == 0) s_mx = red[0];
    __syncthreads();
    float mx = s_mx;

    float e = (tid <= qi) ? expf(val - mx) : 0.f;
    red[tid] = e; __syncthreads();
    for (int st = 128; st > 0; st >>= 1) { if (tid < st) red[tid] += red[tid + st]; __syncthreads(); }
    if (tid == 0) s_sum = red[0];
    __syncthreads();

    w[tid] = e / s_sum;
}

// ---------------- [B,H,T,HS] -> [B,T,C] ----------------
__global__ void transpose_kernel(const float* __restrict__ a, float* __restrict__ at) {
    int i = blockIdx.x * blockDim.x + threadIdx.x;
    if (i >= BT * CC) return;
    int bt = i / CC, c = i % CC;
    int b = bt / TT, t = bt % TT, h = c / HS, d = c % HS;
    at[i] = a[(((size_t)b * HH + h) * TT + t) * HS + d];
}

// ---------------- loss ----------------
__global__ void rowloss_kernel(const float* __restrict__ logits,
                               const int* __restrict__ targets,
                               float* __restrict__ rowloss) {
    int r = blockIdx.x;
    const float* lr = logits + (size_t)r * VV;
    int tid = threadIdx.x;
    __shared__ float red[256];
    __shared__ float s_mx;

    float mx = -1e30f;
    for (int c = tid; c < VV; c += 256) mx = fmaxf(mx, lr[c]);
    red[tid] = mx; __syncthreads();
    for (int st = 128; st > 0; st >>= 1) { if (tid < st) red[tid] = fmaxf(red[tid], red[tid + st]); __syncthreads(); }
    if (tid == 0) s_mx = red[0];
    __syncthreads();
    mx = s_mx;

    float s = 0.f;
    for (int c = tid; c < VV; c += 256) s += expf(lr[c] - mx);
    red[tid] = s; __syncthreads();
    for (int st = 128; st > 0; st >>= 1) { if (tid < st) red[tid] += red[tid + st]; __syncthreads(); }
    if (tid == 0) {
        int t = targets[r];
        rowloss[r] = -(lr[t] - mx - logf(red[0]));
    }
}

__global__ void lossreduce_kernel(const float* __restrict__ rowloss, float* __restrict__ out) {
    __shared__ float red[256];
    int tid = threadIdx.x;
    float s = 0.f;
    for (int r = tid; r < BT; r += 256) s += rowloss[r];
    red[tid] = s; __syncthreads();
    for (int st = 128; st > 0; st >>= 1) { if (tid < st) red[tid] += red[tid + st]; __syncthreads(); }
    if (tid == 0) out[0] = red[0] / BT;
}

// ---------------- host orchestration ----------------
static inline dim3 ggrid(int M, int N, int batch) {
    return dim3((N + 127) / 128, (M + 127) / 128, batch);
}

extern "C" void kernel_launch(void* const* d_in, const int* in_sizes, int n_in,
                              void* d_out, int out_size) {
    const int*   idx     = (const int*)  d_in[0];
    const int*   targets = (const int*)  d_in[1];
    const float* tok_emb = (const float*)d_in[2];
    const float* pos_emb = (const float*)d_in[3];
    const float* Wq      = (const float*)d_in[4];
    const float* Wk      = (const float*)d_in[5];
    const float* Wv      = (const float*)d_in[6];
    const float* Wproj   = (const float*)d_in[7];
    const float* bproj   = (const float*)d_in[8];
    const float* W1      = (const float*)d_in[9];
    const float* b1      = (const float*)d_in[10];
    const float* W2      = (const float*)d_in[11];
    const float* b2      = (const float*)d_in[12];
    const float* ln1_g   = (const float*)d_in[13];
    const float* ln1_b   = (const float*)d_in[14];
    const float* ln2_g   = (const float*)d_in[15];
    const float* ln2_b   = (const float*)d_in[16];
    const float* lnf_g   = (const float*)d_in[17];
    const float* lnf_b   = (const float*)d_in[18];
    const float* Wlm     = (const float*)d_in[19];
    const float* blm     = (const float*)d_in[20];
    float* out = (float*)d_out;

    float* x  = nullptr; cudaGetSymbolAddress((void**)&x,  g_x);
    float* h  = nullptr; cudaGetSymbolAddress((void**)&h,  g_h);
    float* q  = nullptr; cudaGetSymbolAddress((void**)&q,  g_q);
    float* k  = nullptr; cudaGetSymbolAddress((void**)&k,  g_k);
    float* v  = nullptr; cudaGetSymbolAddress((void**)&v,  g_v);
    float* att= nullptr; cudaGetSymbolAddress((void**)&att,g_att);
    float* a  = nullptr; cudaGetSymbolAddress((void**)&a,  g_a);
    float* at = nullptr; cudaGetSymbolAddress((void**)&at, g_at);
    float* ff = nullptr; cudaGetSymbolAddress((void**)&ff, g_ff);
    float* rowloss = nullptr; cudaGetSymbolAddress((void**)&rowloss, g_rowloss);

    const float rs = rsqrtf((float)HS);

    embed_kernel<<<(BT * CC + 255) / 256, 256>>>(idx, tok_emb, pos_emb, x);

    for (int l = 0; l < LL; l++) {
        const float* wq = Wq + (size_t)l * CC * CC;
        const float* wk = Wk + (size_t)l * CC * CC;
        const float* wv = Wv + (size_t)l * CC * CC;
        const float* wp = Wproj + (size_t)l * CC * CC;
        const float* bp = bproj + (size_t)l * CC;
        const float* w1 = W1 + (size_t)l * CC * FFD;
        const float* bb1 = b1 + (size_t)l * FFD;
        const float* w2 = W2 + (size_t)l * FFD * CC;
        const float* bb2 = b2 + (size_t)l * CC;

        ln_kernel<<<BT, 256>>>(x, ln1_g + (size_t)l * CC, ln1_b + (size_t)l * CC, h);

        gemm_tc<false,false,false,false,true><<<ggrid(BT, CC, 1), 256>>>(h, wq, nullptr, q, BT, CC, CC, 1.f, 0, 0, 0);
        gemm_tc<false,false,false,false,true><<<ggrid(BT, CC, 1), 256>>>(h, wk, nullptr, k, BT, CC, CC, 1.f, 0, 0, 0);
        gemm_tc<false,false,false,false,true><<<ggrid(BT, CC, 1), 256>>>(h, wv, nullptr, v, BT, CC, CC, 1.f, 0, 0, 0);

        // scores = Q @ K^T * rs  (batched over B*H)
        gemm_tc<true,false,false,false,false><<<ggrid(TT, TT, BB * HH), 256>>>(
            q, k, nullptr, att, TT, TT, HS, rs,
            (size_t)TT * HS, (size_t)TT * HS, (size_t)TT * TT);

        softmax_kernel<<<BB * HH * TT, 256>>>(att);

        // A = softmax @ V  (batched)
        gemm_tc<false,false,false,false,false><<<ggrid(TT, HS, BB * HH), 256>>>(
            att, v, nullptr, a, TT, HS, TT, 1.f,
            (size_t)TT * TT, (size_t)TT * HS, (size_t)TT * HS);

        transpose_kernel<<<(BT * CC + 255) / 256, 256>>>(a, at);

        // x += at @ Wproj + bproj
        gemm_tc<false,true,false,true,false><<<ggrid(BT, CC, 1), 256>>>(at, wp, bp, x, BT, CC, CC, 1.f, 0, 0, 0);

        ln_kernel<<<BT, 256>>>(x, ln2_g + (size_t)l * CC, ln2_b + (size_t)l * CC, h);

        // ff = relu(h @ W1 + b1)
        gemm_tc<false,true,true,false,false><<<ggrid(BT, FFD, 1), 256>>>(h, w1, bb1, ff, BT, FFD, CC, 1.f, 0, 0, 0);

        // x += ff @ W2 + b2
        gemm_tc<false,true,false,true,false><<<ggrid(BT, CC, 1), 256>>>(ff, w2, bb2, x, BT, CC, FFD, 1.f, 0, 0, 0);
    }

    ln_kernel<<<BT, 256>>>(x, lnf_g, lnf_b, h);

    // logits = h @ Wlm + blm
    gemm_tc<false,true,false,false,false><<<ggrid(BT, VV, 1), 256>>>(h, Wlm, blm, out, BT, VV, CC, 1.f, 0, 0, 0);

    rowloss_kernel<<<BT, 256>>>(out, targets, rowloss);
    if ((long long)out_size > (long long)BT * VV) {
        lossreduce_kernel<<<1, 256>>>(rowloss, out + (size_t)BT * VV);
    }
}

// round 3
// speedup vs baseline: 3.8731x; 1.4511x over previous
#include <cuda_runtime.h>
#include <math.h>
#include <stdint.h>

// ---------------- problem constants ----------------
constexpr int BB = 32, TT = 256, VV = 30522, CC = 768, HH = 8, LL = 10;
constexpr int HS = CC / HH;     // 96
constexpr int FFD = 4 * CC;     // 3072
constexpr int BT = BB * TT;     // 8192
constexpr float LN_EPS = 1e-5f;

// ---------------- scratch ----------------
__device__ float g_x[BT * CC];
__device__ float g_h[BT * CC];
__device__ float g_q[BT * CC];          // [B,H,T,HS]
__device__ float g_k[BT * CC];          // [B,H,T,HS]
__device__ float g_v[BT * CC];          // [B,H,T,HS]
__device__ float g_att[(size_t)BB * HH * TT * TT];
__device__ float g_a[BT * CC];          // [B,H,T,HS]
__device__ float g_ff[(size_t)BT * FFD];
__device__ float g_rowloss[BT];

__device__ __forceinline__ float to_tf32(float x) {
    uint32_t u;
    asm("cvt.rna.tf32.f32 %0, %1;" : "=r"(u) : "f"(x));
    return __uint_as_float(u);
}

__device__ __forceinline__ void mma_tf32(float d[4], const uint32_t a[4], const uint32_t b[2]) {
    asm volatile(
        "mma.sync.aligned.m16n8k8.row.col.f32.tf32.tf32.f32 "
        "{%0,%1,%2,%3}, {%4,%5,%6,%7}, {%8,%9}, {%0,%1,%2,%3};\n"
        : "+f"(d[0]), "+f"(d[1]), "+f"(d[2]), "+f"(d[3])
        : "r"(a[0]), "r"(a[1]), "r"(a[2]), "r"(a[3]), "r"(b[0]), "r"(b[1]));
}

// ---------------- embedding ----------------
__global__ void embed_kernel(const int* __restrict__ idx,
                             const float* __restrict__ tok,
                             const float* __restrict__ pos,
                             float* __restrict__ x) {
    int i = blockIdx.x * blockDim.x + threadIdx.x;
    if (i >= BT * CC) return;
    int bt = i / CC, c = i % CC;
    int t = bt % TT;
    x[i] = tok[(size_t)idx[bt] * CC + c] + pos[(size_t)t * CC + c];
}

// ---------------- layernorm ----------------
__global__ void ln_kernel(const float* __restrict__ x,
                          const float* __restrict__ g,
                          const float* __restrict__ b,
                          float* __restrict__ out) {
    int row = blockIdx.x;
    const float* xr = x + (size_t)row * CC;
    float* orow = out + (size_t)row * CC;
    __shared__ float red[256];
    __shared__ float s_mu, s_inv;
    int tid = threadIdx.x;

    float s = 0.f;
    for (int c = tid; c < CC; c += 256) s += xr[c];
    red[tid] = s; __syncthreads();
    for (int st = 128; st > 0; st >>= 1) { if (tid < st) red[tid] += red[tid + st]; __syncthreads(); }
    if (tid == 0) s_mu = red[0] / CC;
    __syncthreads();
    float mu = s_mu;

    float v = 0.f;
    for (int c = tid; c < CC; c += 256) { float d = xr[c] - mu; v += d * d; }
    red[tid] = v; __syncthreads();
    for (int st = 128; st > 0; st >>= 1) { if (tid < st) red[tid] += red[tid + st]; __syncthreads(); }
    if (tid == 0) s_inv = rsqrtf(red[0] / CC + LN_EPS);
    __syncthreads();
    float inv = s_inv;

    for (int c = tid; c < CC; c += 256)
        orow[c] = (xr[c] - mu) * inv * g[c] + b[c];
}

// ---------------- tensor-core GEMM, register-prefetch pipelined ----------------
// C[M,N] = alpha * A @ B (+bias) (+relu) (+=C if ACC)
// TB:   B stored [N,K] (A @ B^T)
// QKV:  scatter C into [B,H,T,HS]
// AQKV: gather A from [B,H,T,HS] (row-major logical [BT, C])
// All call sites: M % 128 == 0, K % 16 == 0.
template<bool TB, bool BIAS, bool RELU, bool ACC, bool QKV, bool AQKV>
__global__ __launch_bounds__(256, 2)
void gemm_tc(const float* __restrict__ A, const float* __restrict__ Bm,
             const float* __restrict__ bias, float* __restrict__ Cm,
             int M, int N, int K, float alpha,
             size_t sA, size_t sB, size_t sC) {
    constexpr int BM = 128, BN = 128, BK = 16;
    __shared__ float As[BM][BK + 4];    // stride 20
    __shared__ float Bs[BK][BN + 8];    // stride 136

    const float* Ab = A + (size_t)blockIdx.z * sA;
    const float* Bb = Bm + (size_t)blockIdx.z * sB;
    float* Cb = Cm + (size_t)blockIdx.z * sC;

    int bm = blockIdx.y * BM;
    int bn = blockIdx.x * BN;
    int tid = threadIdx.x;
    int wid = tid >> 5, lane = tid & 31;
    int wm = (wid & 1) * 64;
    int wn = (wid >> 1) * 32;
    int gq = lane >> 2;
    int cq = lane & 3;

    // B vector-load feasibility for the [K,N] layout
    const bool bvec = (!TB) && (bn + BN <= N) && ((N & 3) == 0);

    float acc[4][4][4];
    #pragma unroll
    for (int i = 0; i < 4; i++)
        #pragma unroll
        for (int j = 0; j < 4; j++)
            #pragma unroll
            for (int t = 0; t < 4; t++) acc[i][j][t] = 0.f;

    float4 rA[2], rB[2];

    auto loadA = [&](int k0) {
        #pragma unroll
        for (int r = 0; r < 2; r++) {
            int id = tid + r * 256;
            int m = id >> 2, kk = (id & 3) * 4;
            int row = bm + m, gk = k0 + kk;
            const float* src;
            if (AQKV) {
                int b = row / TT, t = row % TT, h = gk / HS, d = gk % HS;
                src = &Ab[(((size_t)b * HH + h) * TT + t) * HS + d];
            } else {
                src = &Ab[(size_t)row * K + gk];
            }
            rA[r] = *reinterpret_cast<const float4*>(src);
        }
    };
    auto storeA = [&]() {
        #pragma unroll
        for (int r = 0; r < 2; r++) {
            int id = tid + r * 256;
            int m = id >> 2, kk = (id & 3) * 4;
            As[m][kk + 0] = to_tf32(rA[r].x);
            As[m][kk + 1] = to_tf32(rA[r].y);
            As[m][kk + 2] = to_tf32(rA[r].z);
            As[m][kk + 3] = to_tf32(rA[r].w);
        }
    };
    auto loadB = [&](int k0) {
        if (!TB) {
            #pragma unroll
            for (int r = 0; r < 2; r++) {
                int id = tid + r * 256;
                int kk = id >> 5;
                int n4 = (id & 31) * 4;
                if (bvec) {
                    rB[r] = *reinterpret_cast<const float4*>(&Bb[(size_t)(k0 + kk) * N + bn + n4]);
                } else {
                    float tmp[4];
                    #pragma unroll
                    for (int j = 0; j < 4; j++) {
                        int gn = bn + n4 + j;
                        tmp[j] = (gn < N) ? Bb[(size_t)(k0 + kk) * N + gn] : 0.f;
                    }
                    rB[r] = make_float4(tmp[0], tmp[1], tmp[2], tmp[3]);
                }
            }
        } else {
            #pragma unroll
            for (int r = 0; r < 2; r++) {
                int id = tid + r * 256;
                int n = id >> 2, kk = (id & 3) * 4;
                if (bn + n < N) {
                    rB[r] = *reinterpret_cast<const float4*>(&Bb[(size_t)(bn + n) * K + k0 + kk]);
                } else {
                    rB[r] = make_float4(0.f, 0.f, 0.f, 0.f);
                }
            }
        }
    };
    auto storeB = [&]() {
        if (!TB) {
            #pragma unroll
            for (int r = 0; r < 2; r++) {
                int id = tid + r * 256;
                int kk = id >> 5;
                int n4 = (id & 31) * 4;
                Bs[kk][n4 + 0] = to_tf32(rB[r].x);
                Bs[kk][n4 + 1] = to_tf32(rB[r].y);
                Bs[kk][n4 + 2] = to_tf32(rB[r].z);
                Bs[kk][n4 + 3] = to_tf32(rB[r].w);
            }
        } else {
            #pragma unroll
            for (int r = 0; r < 2; r++) {
                int id = tid + r * 256;
                int n = id >> 2, kk = (id & 3) * 4;
                Bs[kk + 0][n] = to_tf32(rB[r].x);
                Bs[kk + 1][n] = to_tf32(rB[r].y);
                Bs[kk + 2][n] = to_tf32(rB[r].z);
                Bs[kk + 3][n] = to_tf32(rB[r].w);
            }
        }
    };

    // prologue
    loadA(0); loadB(0);
    storeA(); storeB();
    __syncthreads();

    for (int k0 = 0; k0 < K; k0 += BK) {
        bool has_next = (k0 + BK) < K;
        if (has_next) { loadA(k0 + BK); loadB(k0 + BK); }   // LDGs in flight over MMAs

        #pragma unroll
        for (int kk = 0; kk < BK; kk += 8) {
            uint32_t af[4][4];
            uint32_t bf[4][2];
            #pragma unroll
            for (int i = 0; i < 4; i++) {
                int mr = wm + i * 16;
                af[i][0] = __float_as_uint(As[mr + gq][kk + cq]);
                af[i][1] = __float_as_uint(As[mr + gq + 8][kk + cq]);
                af[i][2] = __float_as_uint(As[mr + gq][kk + cq + 4]);
                af[i][3] = __float_as_uint(As[mr + gq + 8][kk + cq + 4]);
            }
            #pragma unroll
            for (int j = 0; j < 4; j++) {
                int nc = wn + j * 8 + gq;
                bf[j][0] = __float_as_uint(Bs[kk + cq][nc]);
                bf[j][1] = __float_as_uint(Bs[kk + cq + 4][nc]);
            }
            #pragma unroll
            for (int i = 0; i < 4; i++)
                #pragma unroll
                for (int j = 0; j < 4; j++)
                    mma_tf32(acc[i][j], af[i], bf[j]);
        }
        __syncthreads();
        if (has_next) {
            storeA(); storeB();
            __syncthreads();
        }
    }

    // epilogue
    #pragma unroll
    for (int i = 0; i < 4; i++) {
        int r0 = bm + wm + i * 16 + gq;
        #pragma unroll
        for (int j = 0; j < 4; j++) {
            int c0 = bn + wn + j * 8 + cq * 2;
            if (c0 >= N) continue;
            #pragma unroll
            for (int half = 0; half < 2; half++) {
                int row = r0 + half * 8;
                float v0 = acc[i][j][half * 2 + 0] * alpha;
                float v1 = acc[i][j][half * 2 + 1] * alpha;
                if (BIAS) { v0 += bias[c0]; v1 += bias[c0 + 1]; }
                if (RELU) { v0 = fmaxf(v0, 0.f); v1 = fmaxf(v1, 0.f); }
                size_t oidx;
                if (QKV) {
                    int b = row / TT, t = row % TT, h = c0 / HS, d = c0 % HS;
                    oidx = (((size_t)b * HH + h) * TT + t) * HS + d;
                } else {
                    oidx = (size_t)row * N + c0;
                }
                if (ACC) {
                    float2 old = *reinterpret_cast<float2*>(&Cb[oidx]);
                    v0 += old.x; v1 += old.y;
                }
                *reinterpret_cast<float2*>(&Cb[oidx]) = make_float2(v0, v1);
            }
        }
    }
}

// ---------------- causal softmax: one warp per row ----------------
__global__ void softmax_kernel(float* __restrict__ att) {
    int warp = threadIdx.x >> 5, lane = threadIdx.x & 31;
    size_t row = (size_t)blockIdx.x * 8 + warp;
    int qi = (int)(row % TT);
    float* w = att + row * (size_t)TT;

    int i0 = lane * 4, i1 = 128 + lane * 4;
    float4 a0 = *reinterpret_cast<float4*>(&w[i0]);
    float4 a1 = *reinterpret_cast<float4*>(&w[i1]);
    float v[8] = {a0.x, a0.y, a0.z, a0.w, a1.x, a1.y, a1.z, a1.w};
    int base[2] = {i0, i1};

    float mx = -1e30f;
    #pragma unroll
    for (int h = 0; h < 2; h++)
        #pragma unroll
        for (int j = 0; j < 4; j++)
            if (base[h] + j <= qi) mx = fmaxf(mx, v[h * 4 + j]);
    #pragma unroll
    for (int s = 16; s > 0; s >>= 1) mx = fmaxf(mx, __shfl_xor_sync(0xffffffffu, mx, s));

    float e[8];
    float sum = 0.f;
    #pragma unroll
    for (int h = 0; h < 2; h++)
        #pragma unroll
        for (int j = 0; j < 4; j++) {
            int idx = h * 4 + j;
            e[idx] = (base[h] + j <= qi) ? expf(v[idx] - mx) : 0.f;
            sum += e[idx];
        }
    #pragma unroll
    for (int s = 16; s > 0; s >>= 1) sum += __shfl_xor_sync(0xffffffffu, sum, s);
    float inv = 1.f / sum;

    *reinterpret_cast<float4*>(&w[i0]) = make_float4(e[0] * inv, e[1] * inv, e[2] * inv, e[3] * inv);
    *reinterpret_cast<float4*>(&w[i1]) = make_float4(e[4] * inv, e[5] * inv, e[6] * inv, e[7] * inv);
}

// ---------------- loss ----------------
__global__ void rowloss_kernel(const float* __restrict__ logits,
                               const int* __restrict__ targets,
                               float* __restrict__ rowloss) {
    int r = blockIdx.x;
    const float* lr = logits + (size_t)r * VV;
    int tid = threadIdx.x;
    __shared__ float red[256];
    __shared__ float s_mx;

    float mx = -1e30f;
    for (int c = tid; c < VV; c += 256) mx = fmaxf(mx, lr[c]);
    red[tid] = mx; __syncthreads();
    for (int st = 128; st > 0; st >>= 1) { if (tid < st) red[tid] = fmaxf(red[tid], red[tid + st]); __syncthreads(); }
    if (tid == 0) s_mx = red[0];
    __syncthreads();
    mx = s_mx;

    float s = 0.f;
    for (int c = tid; c < VV; c += 256) s += expf(lr[c] - mx);
    red[tid] = s; __syncthreads();
    for (int st = 128; st > 0; st >>= 1) { if (tid < st) red[tid] += red[tid + st]; __syncthreads(); }
    if (tid == 0) {
        int t = targets[r];
        rowloss[r] = -(lr[t] - mx - logf(red[0]));
    }
}

__global__ void lossreduce_kernel(const float* __restrict__ rowloss, float* __restrict__ out) {
    __shared__ float red[256];
    int tid = threadIdx.x;
    float s = 0.f;
    for (int r = tid; r < BT; r += 256) s += rowloss[r];
    red[tid] = s; __syncthreads();
    for (int st = 128; st > 0; st >>= 1) { if (tid < st) red[tid] += red[tid + st]; __syncthreads(); }
    if (tid == 0) out[0] = red[0] / BT;
}

// ---------------- host ----------------
static inline dim3 ggrid(int M, int N, int batch) {
    return dim3((N + 127) / 128, (M + 127) / 128, batch);
}

extern "C" void kernel_launch(void* const* d_in, const int* in_sizes, int n_in,
                              void* d_out, int out_size) {
    const int*   idx     = (const int*)  d_in[0];
    const int*   targets = (const int*)  d_in[1];
    const float* tok_emb = (const float*)d_in[2];
    const float* pos_emb = (const float*)d_in[3];
    const float* Wq      = (const float*)d_in[4];
    const float* Wk      = (const float*)d_in[5];
    const float* Wv      = (const float*)d_in[6];
    const float* Wproj   = (const float*)d_in[7];
    const float* bproj   = (const float*)d_in[8];
    const float* W1      = (const float*)d_in[9];
    const float* b1      = (const float*)d_in[10];
    const float* W2      = (const float*)d_in[11];
    const float* b2      = (const float*)d_in[12];
    const float* ln1_g   = (const float*)d_in[13];
    const float* ln1_b   = (const float*)d_in[14];
    const float* ln2_g   = (const float*)d_in[15];
    const float* ln2_b   = (const float*)d_in[16];
    const float* lnf_g   = (const float*)d_in[17];
    const float* lnf_b   = (const float*)d_in[18];
    const float* Wlm     = (const float*)d_in[19];
    const float* blm     = (const float*)d_in[20];
    float* out = (float*)d_out;

    float* x  = nullptr; cudaGetSymbolAddress((void**)&x,  g_x);
    float* h  = nullptr; cudaGetSymbolAddress((void**)&h,  g_h);
    float* q  = nullptr; cudaGetSymbolAddress((void**)&q,  g_q);
    float* k  = nullptr; cudaGetSymbolAddress((void**)&k,  g_k);
    float* v  = nullptr; cudaGetSymbolAddress((void**)&v,  g_v);
    float* att= nullptr; cudaGetSymbolAddress((void**)&att,g_att);
    float* a  = nullptr; cudaGetSymbolAddress((void**)&a,  g_a);
    float* ff = nullptr; cudaGetSymbolAddress((void**)&ff, g_ff);
    float* rowloss = nullptr; cudaGetSymbolAddress((void**)&rowloss, g_rowloss);

    const float rs = rsqrtf((float)HS);

    embed_kernel<<<(BT * CC + 255) / 256, 256>>>(idx, tok_emb, pos_emb, x);

    for (int l = 0; l < LL; l++) {
        const float* wq = Wq + (size_t)l * CC * CC;
        const float* wk = Wk + (size_t)l * CC * CC;
        const float* wv = Wv + (size_t)l * CC * CC;
        const float* wp = Wproj + (size_t)l * CC * CC;
        const float* bp = bproj + (size_t)l * CC;
        const float* w1 = W1 + (size_t)l * CC * FFD;
        const float* bb1 = b1 + (size_t)l * FFD;
        const float* w2 = W2 + (size_t)l * FFD * CC;
        const float* bb2 = b2 + (size_t)l * CC;

        ln_kernel<<<BT, 256>>>(x, ln1_g + (size_t)l * CC, ln1_b + (size_t)l * CC, h);

        gemm_tc<false,false,false,false,true,false><<<ggrid(BT, CC, 1), 256>>>(h, wq, nullptr, q, BT, CC, CC, 1.f, 0, 0, 0);
        gemm_tc<false,false,false,false,true,false><<<ggrid(BT, CC, 1), 256>>>(h, wk, nullptr, k, BT, CC, CC, 1.f, 0, 0, 0);
        gemm_tc<false,false,false,false,true,false><<<ggrid(BT, CC, 1), 256>>>(h, wv, nullptr, v, BT, CC, CC, 1.f, 0, 0, 0);

        // scores = Q @ K^T * rs  (batched over B*H)
        gemm_tc<true,false,false,false,false,false><<<ggrid(TT, TT, BB * HH), 256>>>(
            q, k, nullptr, att, TT, TT, HS, rs,
            (size_t)TT * HS, (size_t)TT * HS, (size_t)TT * TT);

        softmax_kernel<<<BB * HH * TT / 8, 256>>>(att);

        // A = softmax @ V  (batched)
        gemm_tc<false,false,false,false,false,false><<<ggrid(TT, HS, BB * HH), 256>>>(
            att, v, nullptr, a, TT, HS, TT, 1.f,
            (size_t)TT * TT, (size_t)TT * HS, (size_t)TT * HS);

        // x += attn_out @ Wproj + bproj   (A gathered from [B,H,T,HS])
        gemm_tc<false,true,false,true,false,true><<<ggrid(BT, CC, 1), 256>>>(a, wp, bp, x, BT, CC, CC, 1.f, 0, 0, 0);

        ln_kernel<<<BT, 256>>>(x, ln2_g + (size_t)l * CC, ln2_b + (size_t)l * CC, h);

        // ff = relu(h @ W1 + b1)
        gemm_tc<false,true,true,false,false,false><<<ggrid(BT, FFD, 1), 256>>>(h, w1, bb1, ff, BT, FFD, CC, 1.f, 0, 0, 0);

        // x += ff @ W2 + b2
        gemm_tc<false,true,false,true,false,false><<<ggrid(BT, CC, 1), 256>>>(ff, w2, bb2, x, BT, CC, FFD, 1.f, 0, 0, 0);
    }

    ln_kernel<<<BT, 256>>>(x, lnf_g, lnf_b, h);

    // logits = h @ Wlm + blm
    gemm_tc<false,true,false,false,false,false><<<ggrid(BT, VV, 1), 256>>>(h, Wlm, blm, out, BT, VV, CC, 1.f, 0, 0, 0);

    rowloss_kernel<<<BT, 256>>>(out, targets, rowloss);
    if ((long long)out_size > (long long)BT * VV) {
        lossreduce_kernel<<<1, 256>>>(rowloss, out + (size_t)BT * VV);
    }
}

// round 4
// speedup vs baseline: 3.9132x; 1.0104x over previous
#include <cuda_runtime.h>
#include <math.h>
#include <stdint.h>

// ---------------- problem constants ----------------
constexpr int BB = 32, TT = 256, VV = 30522, CC = 768, HH = 8, LL = 10;
constexpr int HS = CC / HH;     // 96
constexpr int FFD = 4 * CC;     // 3072
constexpr int BT = BB * TT;     // 8192
constexpr float LN_EPS = 1e-5f;

// ---------------- scratch ----------------
__device__ float g_x[BT * CC];
__device__ float g_h[BT * CC];
__device__ float g_q[BT * CC];          // [B,H,T,HS]
__device__ float g_k[BT * CC];          // [B,H,T,HS]
__device__ float g_v[BT * CC];          // [B,H,T,HS]
__device__ float g_att[(size_t)BB * HH * TT * TT];
__device__ float g_a[BT * CC];          // [B,H,T,HS]
__device__ float g_ff[(size_t)BT * FFD];
__device__ float g_rowloss[BT];

__device__ __forceinline__ float to_tf32(float x) {
    uint32_t u;
    asm("cvt.rna.tf32.f32 %0, %1;" : "=r"(u) : "f"(x));
    return __uint_as_float(u);
}

__device__ __forceinline__ void mma_tf32(float d[4], const uint32_t a[4], const uint32_t b[2]) {
    asm volatile(
        "mma.sync.aligned.m16n8k8.row.col.f32.tf32.tf32.f32 "
        "{%0,%1,%2,%3}, {%4,%5,%6,%7}, {%8,%9}, {%0,%1,%2,%3};\n"
        : "+f"(d[0]), "+f"(d[1]), "+f"(d[2]), "+f"(d[3])
        : "r"(a[0]), "r"(a[1]), "r"(a[2]), "r"(a[3]), "r"(b[0]), "r"(b[1]));
}

// ---------------- embedding ----------------
__global__ void embed_kernel(const int* __restrict__ idx,
                             const float* __restrict__ tok,
                             const float* __restrict__ pos,
                             float* __restrict__ x) {
    int i = blockIdx.x * blockDim.x + threadIdx.x;
    if (i >= BT * CC) return;
    int bt = i / CC, c = i % CC;
    int t = bt % TT;
    x[i] = tok[(size_t)idx[bt] * CC + c] + pos[(size_t)t * CC + c];
}

// ---------------- layernorm ----------------
__global__ void ln_kernel(const float* __restrict__ x,
                          const float* __restrict__ g,
                          const float* __restrict__ b,
                          float* __restrict__ out) {
    int row = blockIdx.x;
    const float* xr = x + (size_t)row * CC;
    float* orow = out + (size_t)row * CC;
    __shared__ float red[256];
    __shared__ float s_mu, s_inv;
    int tid = threadIdx.x;

    float s = 0.f;
    for (int c = tid; c < CC; c += 256) s += xr[c];
    red[tid] = s; __syncthreads();
    for (int st = 128; st > 0; st >>= 1) { if (tid < st) red[tid] += red[tid + st]; __syncthreads(); }
    if (tid == 0) s_mu = red[0] / CC;
    __syncthreads();
    float mu = s_mu;

    float v = 0.f;
    for (int c = tid; c < CC; c += 256) { float d = xr[c] - mu; v += d * d; }
    red[tid] = v; __syncthreads();
    for (int st = 128; st > 0; st >>= 1) { if (tid < st) red[tid] += red[tid + st]; __syncthreads(); }
    if (tid == 0) s_inv = rsqrtf(red[0] / CC + LN_EPS);
    __syncthreads();
    float inv = s_inv;

    for (int c = tid; c < CC; c += 256)
        orow[c] = (xr[c] - mu) * inv * g[c] + b[c];
}

// ---------------- tensor-core GEMM: reg prefetch + double-buffered smem ----------------
// C[M,N] = alpha * A @ B (+bias) (+relu) (+=C if ACC)
// TB:   B stored [N,K] (A @ B^T)
// QKV:  scatter C into [B,H,T,HS]
// AQKV: gather A from [B,H,T,HS]
// All call sites: M % 128 == 0, K % 16 == 0.
template<bool TB, bool BIAS, bool RELU, bool ACC, bool QKV, bool AQKV>
__global__ __launch_bounds__(256, 2)
void gemm_tc(const float* __restrict__ A, const float* __restrict__ Bm,
             const float* __restrict__ bias, float* __restrict__ Cm,
             int M, int N, int K, float alpha,
             size_t sA, size_t sB, size_t sC) {
    constexpr int BM = 128, BN = 128, BK = 16;
    __shared__ float As[2][BM][BK + 4];    // stride 20
    __shared__ float Bs[2][BK][BN + 8];    // stride 136

    const float* Ab = A + (size_t)blockIdx.z * sA;
    const float* Bb = Bm + (size_t)blockIdx.z * sB;
    float* Cb = Cm + (size_t)blockIdx.z * sC;

    int bm = blockIdx.y * BM;
    int bn = blockIdx.x * BN;
    int tid = threadIdx.x;
    int wid = tid >> 5, lane = tid & 31;
    int wm = (wid & 1) * 64;
    int wn = (wid >> 1) * 32;
    int gq = lane >> 2;
    int cq = lane & 3;

    const bool bvec = (!TB) && (bn + BN <= N) && ((N & 3) == 0);

    float acc[4][4][4];
    #pragma unroll
    for (int i = 0; i < 4; i++)
        #pragma unroll
        for (int j = 0; j < 4; j++)
            #pragma unroll
            for (int t = 0; t < 4; t++) acc[i][j][t] = 0.f;

    float4 rA[2], rB[2];

    auto loadA = [&](int k0) {
        #pragma unroll
        for (int r = 0; r < 2; r++) {
            int id = tid + r * 256;
            int m = id >> 2, kk = (id & 3) * 4;
            int row = bm + m, gk = k0 + kk;
            const float* src;
            if (AQKV) {
                int b = row / TT, t = row % TT, h = gk / HS, d = gk % HS;
                src = &Ab[(((size_t)b * HH + h) * TT + t) * HS + d];
            } else {
                src = &Ab[(size_t)row * K + gk];
            }
            rA[r] = *reinterpret_cast<const float4*>(src);
        }
    };
    auto storeA = [&](int buf) {
        #pragma unroll
        for (int r = 0; r < 2; r++) {
            int id = tid + r * 256;
            int m = id >> 2, kk = (id & 3) * 4;
            As[buf][m][kk + 0] = to_tf32(rA[r].x);
            As[buf][m][kk + 1] = to_tf32(rA[r].y);
            As[buf][m][kk + 2] = to_tf32(rA[r].z);
            As[buf][m][kk + 3] = to_tf32(rA[r].w);
        }
    };
    auto loadB = [&](int k0) {
        if (!TB) {
            #pragma unroll
            for (int r = 0; r < 2; r++) {
                int id = tid + r * 256;
                int kk = id >> 5;
                int n4 = (id & 31) * 4;
                if (bvec) {
                    rB[r] = *reinterpret_cast<const float4*>(&Bb[(size_t)(k0 + kk) * N + bn + n4]);
                } else {
                    float tmp[4];
                    #pragma unroll
                    for (int j = 0; j < 4; j++) {
                        int gn = bn + n4 + j;
                        tmp[j] = (gn < N) ? Bb[(size_t)(k0 + kk) * N + gn] : 0.f;
                    }
                    rB[r] = make_float4(tmp[0], tmp[1], tmp[2], tmp[3]);
                }
            }
        } else {
            #pragma unroll
            for (int r = 0; r < 2; r++) {
                int id = tid + r * 256;
                int n = id >> 2, kk = (id & 3) * 4;
                if (bn + n < N) {
                    rB[r] = *reinterpret_cast<const float4*>(&Bb[(size_t)(bn + n) * K + k0 + kk]);
                } else {
                    rB[r] = make_float4(0.f, 0.f, 0.f, 0.f);
                }
            }
        }
    };
    auto storeB = [&](int buf) {
        if (!TB) {
            #pragma unroll
            for (int r = 0; r < 2; r++) {
                int id = tid + r * 256;
                int kk = id >> 5;
                int n4 = (id & 31) * 4;
                Bs[buf][kk][n4 + 0] = to_tf32(rB[r].x);
                Bs[buf][kk][n4 + 1] = to_tf32(rB[r].y);
                Bs[buf][kk][n4 + 2] = to_tf32(rB[r].z);
                Bs[buf][kk][n4 + 3] = to_tf32(rB[r].w);
            }
        } else {
            #pragma unroll
            for (int r = 0; r < 2; r++) {
                int id = tid + r * 256;
                int n = id >> 2, kk = (id & 3) * 4;
                Bs[buf][kk + 0][n] = to_tf32(rB[r].x);
                Bs[buf][kk + 1][n] = to_tf32(rB[r].y);
                Bs[buf][kk + 2][n] = to_tf32(rB[r].z);
                Bs[buf][kk + 3][n] = to_tf32(rB[r].w);
            }
        }
    };

    // prologue: fill buffer 0
    loadA(0); loadB(0);
    storeA(0); storeB(0);
    __syncthreads();

    int cur = 0;
    for (int k0 = 0; k0 < K; k0 += BK) {
        bool has_next = (k0 + BK) < K;
        if (has_next) { loadA(k0 + BK); loadB(k0 + BK); }   // LDGs fly over MMAs

        #pragma unroll
        for (int kk = 0; kk < BK; kk += 8) {
            uint32_t af[4][4];
            uint32_t bf[4][2];
            #pragma unroll
            for (int i = 0; i < 4; i++) {
                int mr = wm + i * 16;
                af[i][0] = __float_as_uint(As[cur][mr + gq][kk + cq]);
                af[i][1] = __float_as_uint(As[cur][mr + gq + 8][kk + cq]);
                af[i][2] = __float_as_uint(As[cur][mr + gq][kk + cq + 4]);
                af[i][3] = __float_as_uint(As[cur][mr + gq + 8][kk + cq + 4]);
            }
            #pragma unroll
            for (int j = 0; j < 4; j++) {
                int nc = wn + j * 8 + gq;
                bf[j][0] = __float_as_uint(Bs[cur][kk + cq][nc]);
                bf[j][1] = __float_as_uint(Bs[cur][kk + cq + 4][nc]);
            }
            #pragma unroll
            for (int i = 0; i < 4; i++)
                #pragma unroll
                for (int j = 0; j < 4; j++)
                    mma_tf32(acc[i][j], af[i], bf[j]);
        }

        if (has_next) {
            // write next tile into the other buffer — no barrier needed before
            storeA(cur ^ 1); storeB(cur ^ 1);
        }
        __syncthreads();
        cur ^= 1;
    }

    // epilogue
    #pragma unroll
    for (int i = 0; i < 4; i++) {
        int r0 = bm + wm + i * 16 + gq;
        #pragma unroll
        for (int j = 0; j < 4; j++) {
            int c0 = bn + wn + j * 8 + cq * 2;
            if (c0 >= N) continue;
            #pragma unroll
            for (int half = 0; half < 2; half++) {
                int row = r0 + half * 8;
                float v0 = acc[i][j][half * 2 + 0] * alpha;
                float v1 = acc[i][j][half * 2 + 1] * alpha;
                if (BIAS) { v0 += bias[c0]; v1 += bias[c0 + 1]; }
                if (RELU) { v0 = fmaxf(v0, 0.f); v1 = fmaxf(v1, 0.f); }
                size_t oidx;
                if (QKV) {
                    int b = row / TT, t = row % TT, h = c0 / HS, d = c0 % HS;
                    oidx = (((size_t)b * HH + h) * TT + t) * HS + d;
                } else {
                    oidx = (size_t)row * N + c0;
                }
                if (ACC) {
                    float2 old = *reinterpret_cast<float2*>(&Cb[oidx]);
                    v0 += old.x; v1 += old.y;
                }
                *reinterpret_cast<float2*>(&Cb[oidx]) = make_float2(v0, v1);
            }
        }
    }
}

// ---------------- causal softmax: one warp per row ----------------
__global__ void softmax_kernel(float* __restrict__ att) {
    int warp = threadIdx.x >> 5, lane = threadIdx.x & 31;
    size_t row = (size_t)blockIdx.x * 8 + warp;
    int qi = (int)(row % TT);
    float* w = att + row * (size_t)TT;

    int i0 = lane * 4, i1 = 128 + lane * 4;
    float4 a0 = *reinterpret_cast<float4*>(&w[i0]);
    float4 a1 = *reinterpret_cast<float4*>(&w[i1]);
    float v[8] = {a0.x, a0.y, a0.z, a0.w, a1.x, a1.y, a1.z, a1.w};
    int base[2] = {i0, i1};

    float mx = -1e30f;
    #pragma unroll
    for (int h = 0; h < 2; h++)
        #pragma unroll
        for (int j = 0; j < 4; j++)
            if (base[h] + j <= qi) mx = fmaxf(mx, v[h * 4 + j]);
    #pragma unroll
    for (int s = 16; s > 0; s >>= 1) mx = fmaxf(mx, __shfl_xor_sync(0xffffffffu, mx, s));

    float e[8];
    float sum = 0.f;
    #pragma unroll
    for (int h = 0; h < 2; h++)
        #pragma unroll
        for (int j = 0; j < 4; j++) {
            int idx = h * 4 + j;
            e[idx] = (base[h] + j <= qi) ? expf(v[idx] - mx) : 0.f;
            sum += e[idx];
        }
    #pragma unroll
    for (int s = 16; s > 0; s >>= 1) sum += __shfl_xor_sync(0xffffffffu, sum, s);
    float inv = 1.f / sum;

    *reinterpret_cast<float4*>(&w[i0]) = make_float4(e[0] * inv, e[1] * inv, e[2] * inv, e[3] * inv);
    *reinterpret_cast<float4*>(&w[i1]) = make_float4(e[4] * inv, e[5] * inv, e[6] * inv, e[7] * inv);
}

// ---------------- loss ----------------
__global__ void rowloss_kernel(const float* __restrict__ logits,
                               const int* __restrict__ targets,
                               float* __restrict__ rowloss) {
    int r = blockIdx.x;
    const float* lr = logits + (size_t)r * VV;
    int tid = threadIdx.x;
    __shared__ float red[256];
    __shared__ float s_mx;

    float mx = -1e30f;
    for (int c = tid; c < VV; c += 256) mx = fmaxf(mx, lr[c]);
    red[tid] = mx; __syncthreads();
    for (int st = 128; st > 0; st >>= 1) { if (tid < st) red[tid] = fmaxf(red[tid], red[tid + st]); __syncthreads(); }
    if (tid == 0) s_mx = red[0];
    __syncthreads();
    mx = s_mx;

    float s = 0.f;
    for (int c = tid; c < VV; c += 256) s += expf(lr[c] - mx);
    red[tid] = s; __syncthreads();
    for (int st = 128; st > 0; st >>= 1) { if (tid < st) red[tid] += red[tid + st]; __syncthreads(); }
    if (tid == 0) {
        int t = targets[r];
        rowloss[r] = -(lr[t] - mx - logf(red[0]));
    }
}

__global__ void lossreduce_kernel(const float* __restrict__ rowloss, float* __restrict__ out) {
    __shared__ float red[256];
    int tid = threadIdx.x;
    float s = 0.f;
    for (int r = tid; r < BT; r += 256) s += rowloss[r];
    red[tid] = s; __syncthreads();
    for (int st = 128; st > 0; st >>= 1) { if (tid < st) red[tid] += red[tid + st]; __syncthreads(); }
    if (tid == 0) out[0] = red[0] / BT;
}

// ---------------- host ----------------
static inline dim3 ggrid(int M, int N, int batch) {
    return dim3((N + 127) / 128, (M + 127) / 128, batch);
}

extern "C" void kernel_launch(void* const* d_in, const int* in_sizes, int n_in,
                              void* d_out, int out_size) {
    const int*   idx     = (const int*)  d_in[0];
    const int*   targets = (const int*)  d_in[1];
    const float* tok_emb = (const float*)d_in[2];
    const float* pos_emb = (const float*)d_in[3];
    const float* Wq      = (const float*)d_in[4];
    const float* Wk      = (const float*)d_in[5];
    const float* Wv      = (const float*)d_in[6];
    const float* Wproj   = (const float*)d_in[7];
    const float* bproj   = (const float*)d_in[8];
    const float* W1      = (const float*)d_in[9];
    const float* b1      = (const float*)d_in[10];
    const float* W2      = (const float*)d_in[11];
    const float* b2      = (const float*)d_in[12];
    const float* ln1_g   = (const float*)d_in[13];
    const float* ln1_b   = (const float*)d_in[14];
    const float* ln2_g   = (const float*)d_in[15];
    const float* ln2_b   = (const float*)d_in[16];
    const float* lnf_g   = (const float*)d_in[17];
    const float* lnf_b   = (const float*)d_in[18];
    const float* Wlm     = (const float*)d_in[19];
    const float* blm     = (const float*)d_in[20];
    float* out = (float*)d_out;

    float* x  = nullptr; cudaGetSymbolAddress((void**)&x,  g_x);
    float* h  = nullptr; cudaGetSymbolAddress((void**)&h,  g_h);
    float* q  = nullptr; cudaGetSymbolAddress((void**)&q,  g_q);
    float* k  = nullptr; cudaGetSymbolAddress((void**)&k,  g_k);
    float* v  = nullptr; cudaGetSymbolAddress((void**)&v,  g_v);
    float* att= nullptr; cudaGetSymbolAddress((void**)&att,g_att);
    float* a  = nullptr; cudaGetSymbolAddress((void**)&a,  g_a);
    float* ff = nullptr; cudaGetSymbolAddress((void**)&ff, g_ff);
    float* rowloss = nullptr; cudaGetSymbolAddress((void**)&rowloss, g_rowloss);

    const float rs = rsqrtf((float)HS);

    embed_kernel<<<(BT * CC + 255) / 256, 256>>>(idx, tok_emb, pos_emb, x);

    for (int l = 0; l < LL; l++) {
        const float* wq = Wq + (size_t)l * CC * CC;
        const float* wk = Wk + (size_t)l * CC * CC;
        const float* wv = Wv + (size_t)l * CC * CC;
        const float* wp = Wproj + (size_t)l * CC * CC;
        const float* bp = bproj + (size_t)l * CC;
        const float* w1 = W1 + (size_t)l * CC * FFD;
        const float* bb1 = b1 + (size_t)l * FFD;
        const float* w2 = W2 + (size_t)l * FFD * CC;
        const float* bb2 = b2 + (size_t)l * CC;

        ln_kernel<<<BT, 256>>>(x, ln1_g + (size_t)l * CC, ln1_b + (size_t)l * CC, h);

        gemm_tc<false,false,false,false,true,false><<<ggrid(BT, CC, 1), 256>>>(h, wq, nullptr, q, BT, CC, CC, 1.f, 0, 0, 0);
        gemm_tc<false,false,false,false,true,false><<<ggrid(BT, CC, 1), 256>>>(h, wk, nullptr, k, BT, CC, CC, 1.f, 0, 0, 0);
        gemm_tc<false,false,false,false,true,false><<<ggrid(BT, CC, 1), 256>>>(h, wv, nullptr, v, BT, CC, CC, 1.f, 0, 0, 0);

        // scores = Q @ K^T * rs  (batched over B*H)
        gemm_tc<true,false,false,false,false,false><<<ggrid(TT, TT, BB * HH), 256>>>(
            q, k, nullptr, att, TT, TT, HS, rs,
            (size_t)TT * HS, (size_t)TT * HS, (size_t)TT * TT);

        softmax_kernel<<<BB * HH * TT / 8, 256>>>(att);

        // A = softmax @ V  (batched)
        gemm_tc<false,false,false,false,false,false><<<ggrid(TT, HS, BB * HH), 256>>>(
            att, v, nullptr, a, TT, HS, TT, 1.f,
            (size_t)TT * TT, (size_t)TT * HS, (size_t)TT * HS);

        // x += attn_out @ Wproj + bproj   (A gathered from [B,H,T,HS])
        gemm_tc<false,true,false,true,false,true><<<ggrid(BT, CC, 1), 256>>>(a, wp, bp, x, BT, CC, CC, 1.f, 0, 0, 0);

        ln_kernel<<<BT, 256>>>(x, ln2_g + (size_t)l * CC, ln2_b + (size_t)l * CC, h);

        // ff = relu(h @ W1 + b1)
        gemm_tc<false,true,true,false,false,false><<<ggrid(BT, FFD, 1), 256>>>(h, w1, bb1, ff, BT, FFD, CC, 1.f, 0, 0, 0);

        // x += ff @ W2 + b2
        gemm_tc<false,true,false,true,false,false><<<ggrid(BT, CC, 1), 256>>>(ff, w2, bb2, x, BT, CC, FFD, 1.f, 0, 0, 0);
    }

    ln_kernel<<<BT, 256>>>(x, lnf_g, lnf_b, h);

    // logits = h @ Wlm + blm
    gemm_tc<false,true,false,false,false,false><<<ggrid(BT, VV, 1), 256>>>(h, Wlm, blm, out, BT, VV, CC, 1.f, 0, 0, 0);

    rowloss_kernel<<<BT, 256>>>(out, targets, rowloss);
    if ((long long)out_size > (long long)BT * VV) {
        lossreduce_kernel<<<1, 256>>>(rowloss, out + (size_t)BT * VV);
    }
}